// round 14
// baseline (speedup 1.0000x reference)
#include <cuda_runtime.h>
#include <cuda_bf16.h>
#include <math.h>
#include <stdint.h>

// Fused ConstrainedMLP: 262144 x (12 -> 256 relu -> 256 relu -> 12) + constraints.
// R13: bf16 3-term (proven numerics). TROWS=64, 256 threads (8 warps 2Mx4N m32n64).
// A hi/lo resident (64KB) + B-hi FULLY resident (128KB) -> phase 1 (AhBh+AlBh, 2/3
// of mma) runs with ZERO barriers. B-lo then ping-ponged through dead A-lo space
// for phase 2 (AhBl). smem 223KB, 1 CTA/SM.

#define BATCH    262144
#define TROWS    64
#define NTHREAD  256

typedef unsigned long long u64;
typedef unsigned int u32;

// ---------- helpers ----------
__device__ __forceinline__ u64 fma2(u64 a, u64 b, u64 c) {
    u64 d;
    asm("fma.rn.f32x2 %0, %1, %2, %3;" : "=l"(d) : "l"(a), "l"(b), "l"(c));
    return d;
}
__device__ __forceinline__ u64 pack2(float x, float y) {
    u64 r;
    asm("mov.b64 %0, {%1, %2};" : "=l"(r) : "f"(x), "f"(y));
    return r;
}
__device__ __forceinline__ void unpack2(u64 v, float& x, float& y) {
    asm("mov.b64 {%0, %1}, %2;" : "=f"(x), "=f"(y) : "l"(v));
}
__device__ __forceinline__ u32 smem_u32(const void* p) {
    u32 a;
    asm("{ .reg .u64 t; cvta.to.shared.u64 t, %1; cvt.u32.u64 %0, t; }" : "=r"(a) : "l"(p));
    return a;
}
__device__ __forceinline__ void cp_async16(char* smem_dst, const char* gsrc) {
    u32 s = smem_u32(smem_dst);
    asm volatile("cp.async.cg.shared.global [%0], [%1], 16;" :: "r"(s), "l"(gsrc));
}
__device__ __forceinline__ void cp_commit() { asm volatile("cp.async.commit_group;"); }
__device__ __forceinline__ void cp_wait0()  { asm volatile("cp.async.wait_group 0;" ::: "memory"); }

__device__ __forceinline__ void ldsm4(u32& r0, u32& r1, u32& r2, u32& r3, u32 addr) {
    asm volatile("ldmatrix.sync.aligned.m8n8.x4.shared.b16 {%0,%1,%2,%3}, [%4];"
                 : "=r"(r0), "=r"(r1), "=r"(r2), "=r"(r3) : "r"(addr));
}
__device__ __forceinline__ void mma16816(float* d, const u32* a, const u32* b) {
    asm volatile(
        "mma.sync.aligned.m16n8k16.row.col.f32.bf16.bf16.f32 "
        "{%0,%1,%2,%3}, {%4,%5,%6,%7}, {%8,%9}, {%0,%1,%2,%3};"
        : "+f"(d[0]), "+f"(d[1]), "+f"(d[2]), "+f"(d[3])
        : "r"(a[0]), "r"(a[1]), "r"(a[2]), "r"(a[3]), "r"(b[0]), "r"(b[1]));
}

// ---------- W2^T bf16 hi/lo images (layout proven in R6) ----------
// Each image: 8 half-chunks (32 k each) x 16384 B = 131072 B total.
// Per half-chunk: line = n&127 (128 B), slot s = ((kl>>3) + ((n>>7)<<2)) ^ (n&7).
__device__ __align__(128) unsigned short g_W2h[65536];
__device__ __align__(128) unsigned short g_W2l[65536];

__global__ void prep_w2(const float* __restrict__ W2) {
    int i = blockIdx.x * 256 + threadIdx.x;   // i = k*256 + n over W2[k][n]
    int k = i >> 8, n = i & 255;
    float w = W2[i];
    __nv_bfloat16 hb = __float2bfloat16(w);
    __nv_bfloat16 lb = __float2bfloat16(w - __bfloat162float(hb));
    u32 hc = (u32)k >> 5, kl = (u32)k & 31;
    u32 s = ((kl >> 3) + (((u32)n >> 7) << 2)) ^ ((u32)n & 7);
    u32 off = hc * 16384u + ((u32)n & 127) * 128u + s * 16u + (kl & 7) * 2u;
    g_W2h[off >> 1] = __bfloat16_as_ushort(hb);
    g_W2l[off >> 1] = __bfloat16_as_ushort(lb);
}

// ---------- smem byte offsets (total 223296 B, 1 CTA/SM) ----------
#define SA_H    0         // A hi: 4 chunks x 8192 = 32768
#define SA_L    32768     // A lo: 32768 ; REUSED as B-lo ping-pong in phase 2
#define SBH     65536     // B hi FULLY resident: 131072
#define SW1P    196608    // W1 pairs 128*12 u64 = 12288
#define SW3P    208896    // W3 pairs 128*12 u64 = 12288
#define SB1     221184    // 1024
#define SB2     222208    // 1024
#define SMEM_BYTES 223296
#define SPART   SA_H      // layer-3 partials (12288 B) alias A hi (dead after mma)

__global__ __launch_bounds__(NTHREAD, 1)
void mlp_main(const float* __restrict__ inp,
              const float* __restrict__ W1,
              const float* __restrict__ b1,
              const float* __restrict__ b2,
              const float* __restrict__ W3,
              const float* __restrict__ b3,
              float* __restrict__ out)
{
    extern __shared__ char sm[];
    u64*   w3p  = (u64*)  (sm + SW3P);
    u64*   w1p  = (u64*)  (sm + SW1P);
    float* part = (float*)(sm + SPART);
    float* b1s  = (float*)(sm + SB1);
    float* b2s  = (float*)(sm + SB2);
    const u32 smb = smem_u32(sm);
    const int t = threadIdx.x;
    const long rowBase = (long)blockIdx.x * TROWS;

    // ---- prefetch ALL of B hi (128KB) into SBH ----
    {
        const char* src = (const char*)g_W2h;
#pragma unroll
        for (int i = 0; i < 32; i++) {
            int o = (t + i * NTHREAD) * 16;
            cp_async16(sm + SBH + o, src + o);
        }
        cp_commit();
    }

    // ---- staging ----
    for (int i = t; i < 1536; i += NTHREAD) {        // W1 pairs
        int jp = i / 12, k = i % 12;
        w1p[i] = pack2(W1[k * 256 + 2 * jp], W1[k * 256 + 2 * jp + 1]);
    }
    for (int i = t; i < 1536; i += NTHREAD) {        // W3 pairs
        int k2 = i / 12, o = i % 12;
        w3p[i] = pack2(W3[(2 * k2) * 12 + o], W3[(2 * k2 + 1) * 12 + o]);
    }
    for (int i = t; i < 256; i += NTHREAD) { b1s[i] = b1[i]; b2s[i] = b2[i]; }
    __syncthreads();

    // ---- layer 1: thread t -> row r = t&63, units [ug*64, ug*64+64) ----
    {
        const int r = t & 63, ug = t >> 6;
        const float* xrow = inp + (rowBase + r) * 12;
        u64 xx[12];
#pragma unroll
        for (int k = 0; k < 12; k++) { float x = xrow[k]; xx[k] = pack2(x, x); }
        char* ahc = sm + SA_H + ug * 8192;
        char* alc = sm + SA_L + ug * 8192;
#pragma unroll 4
        for (int i = 0; i < 32; i++) {
            const int kl0 = 2 * i;
            const int j = ug * 64 + kl0;
            const u64* wp = w1p + (j >> 1) * 12;
            u64 acc2 = pack2(b1s[j], b1s[j + 1]);
#pragma unroll
            for (int k = 0; k < 12; k++) acc2 = fma2(wp[k], xx[k], acc2);
            float a0, a1;
            unpack2(acc2, a0, a1);
            a0 = fmaxf(a0, 0.0f); a1 = fmaxf(a1, 0.0f);
            __nv_bfloat16 h0 = __float2bfloat16(a0), h1 = __float2bfloat16(a1);
            __nv_bfloat16 l0 = __float2bfloat16(a0 - __bfloat162float(h0));
            __nv_bfloat16 l1 = __float2bfloat16(a1 - __bfloat162float(h1));
            u32 hw = (u32)__bfloat16_as_ushort(h0) | ((u32)__bfloat16_as_ushort(h1) << 16);
            u32 lw = (u32)__bfloat16_as_ushort(l0) | ((u32)__bfloat16_as_ushort(l1) << 16);
            u32 off = ((u32)r << 7) + ((((u32)(kl0 >> 3)) ^ ((u32)r & 7)) << 4) + (((u32)kl0 & 7) << 1);
            *(u32*)(ahc + off) = hw;
            *(u32*)(alc + off) = lw;
        }
    }
    cp_wait0();
    __syncthreads();          // A hi/lo written + B hi resident, visible to all

    // ---- warp mma geometry: 8 warps = 2M x 4N, warp tile m32 x n64 ----
    const int w = t >> 5, lane = t & 31;
    const int m0 = (w & 1) * 32, n0 = (w >> 1) * 64;
    const int lt = lane >> 3, l8 = lane & 7;

    u32 arow[2], asx[2];
#pragma unroll
    for (int a = 0; a < 2; a++) {
        u32 row = (u32)(m0 + a * 16 + ((lt & 1) << 3) + l8);
        arow[a] = row << 7;
        asx[a]  = row & 7;
    }
    const u32 a_kt = (u32)(lt >> 1);
    u32 bline[4], bx[4];
    const u32 bhi = ((u32)n0 >> 7) << 2;
#pragma unroll
    for (int fp = 0; fp < 4; fp++) {
        u32 n = (u32)(n0 + fp * 16 + ((lt >> 1) << 3) + l8);
        bline[fp] = (n & 127) << 7;
        bx[fp]    = n & 7;
    }
    const u32 b_kt = (u32)(lt & 1);

    float acc[2][8][4];
#pragma unroll
    for (int a = 0; a < 2; a++)
#pragma unroll
        for (int f = 0; f < 8; f++)
#pragma unroll
            for (int q = 0; q < 4; q++) acc[a][f][q] = 0.0f;

    // ---- PHASE 1: AhBh + AlBh over 16 k16-steps, ZERO barriers ----
#pragma unroll 4
    for (int s = 0; s < 16; s++) {
        const u32 pAh = smb + SA_H + (u32)(s >> 2) * 8192u;
        const u32 pAl = smb + SA_L + (u32)(s >> 2) * 8192u;
        const u32 pBh = smb + SBH  + (u32)(s >> 1) * 16384u;
        const u32 ktA = (u32)((s & 3) * 2) + a_kt;
        const u32 uB  = (u32)((s & 1) * 2) + b_kt;
        u32 Ah[2][4], Al[2][4], B[4][4];
#pragma unroll
        for (int a = 0; a < 2; a++) {
            u32 ad = arow[a] + ((ktA ^ asx[a]) << 4);
            ldsm4(Ah[a][0], Ah[a][1], Ah[a][2], Ah[a][3], pAh + ad);
            ldsm4(Al[a][0], Al[a][1], Al[a][2], Al[a][3], pAl + ad);
        }
#pragma unroll
        for (int fp = 0; fp < 4; fp++) {
            u32 bd = bline[fp] + (((uB + bhi) ^ bx[fp]) << 4);
            ldsm4(B[fp][0], B[fp][1], B[fp][2], B[fp][3], pBh + bd);
        }
#pragma unroll
        for (int a = 0; a < 2; a++)
#pragma unroll
            for (int fp = 0; fp < 4; fp++) {
                mma16816(acc[a][2 * fp],     Ah[a], &B[fp][0]);
                mma16816(acc[a][2 * fp + 1], Ah[a], &B[fp][2]);
                mma16816(acc[a][2 * fp],     Al[a], &B[fp][0]);
                mma16816(acc[a][2 * fp + 1], Al[a], &B[fp][2]);
            }
    }

    // ---- phase 2 setup: A lo dead; stream B lo through SA_L (2 x 16KB ping-pong) ----
    __syncthreads();                          // everyone done reading A lo
    {
        const char* src = (const char*)g_W2l; // Bl chunk 0
#pragma unroll
        for (int i = 0; i < 4; i++) {
            int o = (t + i * NTHREAD) * 16;
            cp_async16(sm + SA_L + o, src + o);
        }
        cp_commit();
    }

    // ---- PHASE 2: AhBl over 8 Bl chunks (2 k16-steps each) ----
    for (int c = 0; c < 8; c++) {
        cp_wait0();
        __syncthreads();                      // Bl chunk c visible; other half free
        if (c < 7) {
            const char* src = (const char*)g_W2l + (c + 1) * 16384;
            char* dst = sm + SA_L + ((c + 1) & 1) * 16384;
#pragma unroll
            for (int i = 0; i < 4; i++) {
                int o = (t + i * NTHREAD) * 16;
                cp_async16(dst + o, src + o);
            }
            cp_commit();
        }
        const u32 pBl = smb + SA_L + (u32)(c & 1) * 16384u;
#pragma unroll
        for (int ks2 = 0; ks2 < 2; ks2++) {
            const int s = c * 2 + ks2;
            const u32 pAh = smb + SA_H + (u32)(s >> 2) * 8192u;
            const u32 ktA = (u32)((s & 3) * 2) + a_kt;
            const u32 uB  = (u32)(ks2 * 2) + b_kt;
            u32 Ah[2][4], B[4][4];
#pragma unroll
            for (int a = 0; a < 2; a++) {
                u32 ad = arow[a] + ((ktA ^ asx[a]) << 4);
                ldsm4(Ah[a][0], Ah[a][1], Ah[a][2], Ah[a][3], pAh + ad);
            }
#pragma unroll
            for (int fp = 0; fp < 4; fp++) {
                u32 bd = bline[fp] + (((uB + bhi) ^ bx[fp]) << 4);
                ldsm4(B[fp][0], B[fp][1], B[fp][2], B[fp][3], pBl + bd);
            }
#pragma unroll
            for (int a = 0; a < 2; a++)
#pragma unroll
                for (int fp = 0; fp < 4; fp++) {
                    mma16816(acc[a][2 * fp],     Ah[a], &B[fp][0]);
                    mma16816(acc[a][2 * fp + 1], Ah[a], &B[fp][2]);
                }
        }
    }
    __syncthreads();                          // A hi dead -> parts may alias it

    // ---- epilogue: bias + relu + layer-3 partials + quad reduce ----
    {
        const int nw = w >> 1;                 // 0..3
        const int cbase = n0 + (lane & 3) * 2;
#pragma unroll
        for (int a = 0; a < 2; a++) {
#pragma unroll
            for (int h = 0; h < 2; h++) {
                u64 p[12];
#pragma unroll
                for (int o = 0; o < 12; o++) p[o] = 0;
#pragma unroll
                for (int f = 0; f < 8; f++) {
                    const int col = cbase + 8 * f;
                    float h0 = fmaxf(acc[a][f][2 * h]     + b2s[col],     0.0f);
                    float h1 = fmaxf(acc[a][f][2 * h + 1] + b2s[col + 1], 0.0f);
                    const u64 hh = pack2(h0, h1);
                    const u64* wv = w3p + (col >> 1) * 12;
#pragma unroll
                    for (int o = 0; o < 12; o++) p[o] = fma2(wv[o], hh, p[o]);
                }
                float v[12];
#pragma unroll
                for (int o = 0; o < 12; o++) {
                    float lo, hi;
                    unpack2(p[o], lo, hi);
                    v[o] = lo + hi;
                    v[o] += __shfl_xor_sync(0xffffffffu, v[o], 1);
                    v[o] += __shfl_xor_sync(0xffffffffu, v[o], 2);
                }
                if ((lane & 3) == 0) {
                    const int row = m0 + a * 16 + h * 8 + (lane >> 2);
                    float* dst = part + (nw * 64 + row) * 12;
#pragma unroll
                    for (int o = 0; o < 12; o++) dst[o] = v[o];
                }
            }
        }
    }
    __syncthreads();

    // ---- constraint epilogue: threads 0..63, one row each ----
    if (t < TROWS) {
        const float* xi = inp + (rowBase + t) * 12;
        float xo[12];
#pragma unroll
        for (int o = 0; o < 12; o++) {
            xo[o] = __ldg(b3 + o) + part[t * 12 + o] + part[(64 + t) * 12 + o]
                  + part[(128 + t) * 12 + o] + part[(192 + t) * 12 + o];
        }

        float p0 = tanhf(xo[0]), p1 = tanhf(xo[1]), p2 = tanhf(xo[2]);
        float v0 = tanhf(xo[3]), v1 = tanhf(xo[4]), v2 = tanhf(xo[5]);
        float pts = 1.0f / (1.0f + expf(-xo[6]));
        float c0 = tanhf(xo[7]), c1 = tanhf(xo[8]), c2 = tanhf(xo[9]);
        float s0 = tanhf(xo[10]), s1 = tanhf(xo[11]);

        float dist = sqrtf(p0 * p0 + p1 * p1 + p2 * p2);
        float pinv = (dist > 1.0f) ? (1.0f / dist) : 1.0f;
        p0 *= pinv; p1 *= pinv; p2 *= pinv;

        const float prev = xi[6];
        float ptsc = (pts > 1.0f) ? 1.0f : pts;
        ptsc = (pts < prev) ? prev : ptsc;

        const float d0 = c0 - xi[7], d1 = c1 - xi[8], d2 = c2 - xi[9];
        const float e0 = xi[0] - xi[7], e1 = xi[1] - xi[8], e2 = xi[2] - xi[9];
        const float en = sqrtf(e0 * e0 + e1 * e1 + e2 * e2);
        const float n0f = e0 / en, n1f = e1 / en, n2f = e2 / en;
        const float dd = d0 * e0 + d1 * e1 + d2 * e2;
        const float o0 = (dd > 0.0f) ? (c0 - n0f) : c0;
        const float o1 = (dd > 0.0f) ? (c1 - n1f) : c1;
        const float o2 = (dd > 0.0f) ? (c2 - n2f) : c2;
        const float cd = sqrtf(o0 * o0 + o1 * o1 + o2 * o2);
        float q0, q1, q2;
        if (cd > 1.0f) { const float ci = 1.0f / cd; q0 = o0 * ci; q1 = o1 * ci; q2 = o2 * ci; }
        else           { q0 = c0; q1 = c1; q2 = c2; }

        const float sn = sqrtf(s0 * s0 + s1 * s1);
        s0 /= sn; s1 /= sn;

        float* op = out + (rowBase + t) * 12;
        float4* ov = reinterpret_cast<float4*>(op);
        ov[0] = make_float4(p0, p1, p2, v0);
        ov[1] = make_float4(v1, v2, ptsc, q0);
        ov[2] = make_float4(q1, q2, s0, s1);
    }
}

extern "C" void kernel_launch(void* const* d_in, const int* in_sizes, int n_in,
                              void* d_out, int out_size)
{
    (void)in_sizes; (void)n_in; (void)out_size;
    const float* inp = (const float*)d_in[0];
    const float* W1  = (const float*)d_in[1];
    const float* b1  = (const float*)d_in[2];
    const float* W2  = (const float*)d_in[3];
    const float* b2  = (const float*)d_in[4];
    const float* W3  = (const float*)d_in[5];
    const float* b3  = (const float*)d_in[6];
    float* out = (float*)d_out;

    prep_w2<<<256, 256>>>(W2);

    cudaFuncSetAttribute(mlp_main, cudaFuncAttributeMaxDynamicSharedMemorySize, SMEM_BYTES);
    mlp_main<<<BATCH / TROWS, NTHREAD, SMEM_BYTES>>>(inp, W1, b1, b2, W3, b3, out);
}

// round 15
// speedup vs baseline: 1.1047x; 1.1047x over previous
#include <cuda_runtime.h>
#include <cuda_bf16.h>
#include <math.h>
#include <stdint.h>

// Fused ConstrainedMLP: 262144 x (12 -> 256 relu -> 256 relu -> 12) + constraints.
// R14: exact R10 structure (TROWS=64, 256 thr, 8 warps 2Mx4N m32n64, 2 CTAs/SM,
// A hi/lo resident, B streamed 16KB chunks double-buffered) with ONE change:
// mma issue order reorganized so accumulator RAW distance is 16 mma (was 2).

#define BATCH    262144
#define TROWS    64
#define NTHREAD  256

typedef unsigned long long u64;
typedef unsigned int u32;

// ---------- helpers ----------
__device__ __forceinline__ u64 fma2(u64 a, u64 b, u64 c) {
    u64 d;
    asm("fma.rn.f32x2 %0, %1, %2, %3;" : "=l"(d) : "l"(a), "l"(b), "l"(c));
    return d;
}
__device__ __forceinline__ u64 pack2(float x, float y) {
    u64 r;
    asm("mov.b64 %0, {%1, %2};" : "=l"(r) : "f"(x), "f"(y));
    return r;
}
__device__ __forceinline__ void unpack2(u64 v, float& x, float& y) {
    asm("mov.b64 {%0, %1}, %2;" : "=f"(x), "=f"(y) : "l"(v));
}
__device__ __forceinline__ u32 smem_u32(const void* p) {
    u32 a;
    asm("{ .reg .u64 t; cvta.to.shared.u64 t, %1; cvt.u32.u64 %0, t; }" : "=r"(a) : "l"(p));
    return a;
}
__device__ __forceinline__ void cp_async16(char* smem_dst, const char* gsrc) {
    u32 s = smem_u32(smem_dst);
    asm volatile("cp.async.cg.shared.global [%0], [%1], 16;" :: "r"(s), "l"(gsrc));
}
__device__ __forceinline__ void cp_commit() { asm volatile("cp.async.commit_group;"); }
__device__ __forceinline__ void cp_wait0()  { asm volatile("cp.async.wait_group 0;" ::: "memory"); }

__device__ __forceinline__ void ldsm4(u32& r0, u32& r1, u32& r2, u32& r3, u32 addr) {
    asm volatile("ldmatrix.sync.aligned.m8n8.x4.shared.b16 {%0,%1,%2,%3}, [%4];"
                 : "=r"(r0), "=r"(r1), "=r"(r2), "=r"(r3) : "r"(addr));
}
__device__ __forceinline__ void mma16816(float* d, const u32* a, const u32* b) {
    asm volatile(
        "mma.sync.aligned.m16n8k16.row.col.f32.bf16.bf16.f32 "
        "{%0,%1,%2,%3}, {%4,%5,%6,%7}, {%8,%9}, {%0,%1,%2,%3};"
        : "+f"(d[0]), "+f"(d[1]), "+f"(d[2]), "+f"(d[3])
        : "r"(a[0]), "r"(a[1]), "r"(a[2]), "r"(a[3]), "r"(b[0]), "r"(b[1]));
}

// ---------- W2^T bf16 hi/lo images (layout proven in R6) ----------
__device__ __align__(128) unsigned short g_W2h[65536];
__device__ __align__(128) unsigned short g_W2l[65536];

__global__ void prep_w2(const float* __restrict__ W2) {
    int i = blockIdx.x * 256 + threadIdx.x;   // i = k*256 + n over W2[k][n]
    int k = i >> 8, n = i & 255;
    float w = W2[i];
    __nv_bfloat16 hb = __float2bfloat16(w);
    __nv_bfloat16 lb = __float2bfloat16(w - __bfloat162float(hb));
    u32 hc = (u32)k >> 5, kl = (u32)k & 31;
    u32 s = ((kl >> 3) + (((u32)n >> 7) << 2)) ^ ((u32)n & 7);
    u32 off = hc * 16384u + ((u32)n & 127) * 128u + s * 16u + (kl & 7) * 2u;
    g_W2h[off >> 1] = __bfloat16_as_ushort(hb);
    g_W2l[off >> 1] = __bfloat16_as_ushort(lb);
}

// ---------- smem byte offsets (total 112640 B -> 2 CTAs/SM) ----------
#define SA_H    0         // A hi: 32768
#define SA_L    32768     // A lo: 32768
#define SB      65536     // B double buffer: 2 x 16384 = 32768
#define SW3P    98304     // W3 pairs 128*12 u64 = 12288
#define SB1     110592    // 1024
#define SB2     111616    // 1024
#define SMEM_BYTES 112640
#define SW1P    (SB + 16384)   // W1 pairs (12288 B) alias B buf1 (dead after layer 1)
#define SPART   SA_H           // layer-3 partials (12288 B) alias A hi (after all mma)

__global__ __launch_bounds__(NTHREAD, 2)
void mlp_main(const float* __restrict__ inp,
              const float* __restrict__ W1,
              const float* __restrict__ b1,
              const float* __restrict__ b2,
              const float* __restrict__ W3,
              const float* __restrict__ b3,
              float* __restrict__ out)
{
    extern __shared__ char sm[];
    u64*   w3p  = (u64*)  (sm + SW3P);
    u64*   w1p  = (u64*)  (sm + SW1P);
    float* part = (float*)(sm + SPART);
    float* b1s  = (float*)(sm + SB1);
    float* b2s  = (float*)(sm + SB2);
    const u32 smb = smem_u32(sm);
    const int t = threadIdx.x;
    const long rowBase = (long)blockIdx.x * TROWS;

    // ---- prefetch B chunk 0 (hi, k0..31) into buf0 ----
    {
        const char* src = (const char*)g_W2h;
#pragma unroll
        for (int i = 0; i < 4; i++) {
            int o = (t + i * NTHREAD) * 16;
            cp_async16(sm + SB + o, src + o);
        }
        cp_commit();
    }

    // ---- staging ----
    for (int i = t; i < 1536; i += NTHREAD) {        // W1 pairs (alias B buf1)
        int jp = i / 12, k = i % 12;
        w1p[i] = pack2(W1[k * 256 + 2 * jp], W1[k * 256 + 2 * jp + 1]);
    }
    for (int i = t; i < 1536; i += NTHREAD) {        // W3 pairs
        int k2 = i / 12, o = i % 12;
        w3p[i] = pack2(W3[(2 * k2) * 12 + o], W3[(2 * k2 + 1) * 12 + o]);
    }
    for (int i = t; i < 256; i += NTHREAD) { b1s[i] = b1[i]; b2s[i] = b2[i]; }
    __syncthreads();

    // ---- layer 1: thread t -> row r = t&63, units [ug*64, ug*64+64) ----
    {
        const int r = t & 63, ug = t >> 6;
        const float* xrow = inp + (rowBase + r) * 12;
        u64 xx[12];
#pragma unroll
        for (int k = 0; k < 12; k++) { float x = xrow[k]; xx[k] = pack2(x, x); }
        char* ahc = sm + SA_H + ug * 8192;
        char* alc = sm + SA_L + ug * 8192;
#pragma unroll 4
        for (int i = 0; i < 32; i++) {
            const int kl0 = 2 * i;
            const int j = ug * 64 + kl0;
            const u64* wp = w1p + (j >> 1) * 12;
            u64 acc2 = pack2(b1s[j], b1s[j + 1]);
#pragma unroll
            for (int k = 0; k < 12; k++) acc2 = fma2(wp[k], xx[k], acc2);
            float a0, a1;
            unpack2(acc2, a0, a1);
            a0 = fmaxf(a0, 0.0f); a1 = fmaxf(a1, 0.0f);
            __nv_bfloat16 h0 = __float2bfloat16(a0), h1 = __float2bfloat16(a1);
            __nv_bfloat16 l0 = __float2bfloat16(a0 - __bfloat162float(h0));
            __nv_bfloat16 l1 = __float2bfloat16(a1 - __bfloat162float(h1));
            u32 hw = (u32)__bfloat16_as_ushort(h0) | ((u32)__bfloat16_as_ushort(h1) << 16);
            u32 lw = (u32)__bfloat16_as_ushort(l0) | ((u32)__bfloat16_as_ushort(l1) << 16);
            u32 off = ((u32)r << 7) + ((((u32)(kl0 >> 3)) ^ ((u32)r & 7)) << 4) + (((u32)kl0 & 7) << 1);
            *(u32*)(ahc + off) = hw;
            *(u32*)(alc + off) = lw;
        }
    }
    // loop-top sync of c=0 covers: A visible to all, w1p dead before buf1 prefetch.

    // ---- warp mma geometry: 8 warps = 2M x 4N, warp tile m32 x n64 ----
    const int w = t >> 5, lane = t & 31;
    const int m0 = (w & 1) * 32, n0 = (w >> 1) * 64;
    const int lt = lane >> 3, l8 = lane & 7;

    u32 arow[2], asx[2];
#pragma unroll
    for (int a = 0; a < 2; a++) {
        u32 row = (u32)(m0 + a * 16 + ((lt & 1) << 3) + l8);
        arow[a] = row << 7;
        asx[a]  = row & 7;
    }
    const u32 a_kt = (u32)(lt >> 1);
    u32 bline[4], bx[4];
    const u32 bhi = ((u32)n0 >> 7) << 2;
#pragma unroll
    for (int fp = 0; fp < 4; fp++) {
        u32 n = (u32)(n0 + fp * 16 + ((lt >> 1) << 3) + l8);
        bline[fp] = (n & 127) << 7;
        bx[fp]    = n & 7;
    }
    const u32 b_kt = (u32)(lt & 1);

    float acc[2][8][4];
#pragma unroll
    for (int a = 0; a < 2; a++)
#pragma unroll
        for (int f = 0; f < 8; f++)
#pragma unroll
            for (int q = 0; q < 4; q++) acc[a][f][q] = 0.0f;

    // ---- loop 1: chunks 0..7 (B hi), AhBh + AlBh — acc RAW distance 16 ----
    for (int c = 0; c < 8; c++) {
        cp_wait0();
        __syncthreads();                       // chunk c visible; buf (c+1)&1 free
        {
            const char* src = (c + 1 < 8) ? (const char*)g_W2h + (c + 1) * 16384
                                          : (const char*)g_W2l;
            char* dst = sm + SB + ((c + 1) & 1) * 16384;
#pragma unroll
            for (int i = 0; i < 4; i++) {
                int o = (t + i * NTHREAD) * 16;
                cp_async16(dst + o, src + o);
            }
            cp_commit();
        }
        const u32 pB  = smb + SB + (u32)(c & 1) * 16384u;
        const u32 pAh = smb + SA_H + (u32)(c >> 1) * 8192u;
        const u32 pAl = smb + SA_L + (u32)(c >> 1) * 8192u;
#pragma unroll
        for (int ks2 = 0; ks2 < 2; ks2++) {
            const u32 ktA = (u32)(((c & 1) * 2 + ks2) * 2) + a_kt;
            const u32 uB  = (u32)(ks2 * 2) + b_kt;
            u32 Ah[2][4], Al[2][4], B[4][4];
#pragma unroll
            for (int a = 0; a < 2; a++) {
                u32 ad = arow[a] + ((ktA ^ asx[a]) << 4);
                ldsm4(Ah[a][0], Ah[a][1], Ah[a][2], Ah[a][3], pAh + ad);
                ldsm4(Al[a][0], Al[a][1], Al[a][2], Al[a][3], pAl + ad);
            }
#pragma unroll
            for (int fp = 0; fp < 4; fp++) {
                u32 bd = bline[fp] + (((uB + bhi) ^ bx[fp]) << 4);
                ldsm4(B[fp][0], B[fp][1], B[fp][2], B[fp][3], pB + bd);
            }
            // Block 1: Ah x B -> 16 mma, all 16 distinct accumulators
#pragma unroll
            for (int a = 0; a < 2; a++)
#pragma unroll
                for (int fp = 0; fp < 4; fp++) {
                    mma16816(acc[a][2 * fp],     Ah[a], &B[fp][0]);
                    mma16816(acc[a][2 * fp + 1], Ah[a], &B[fp][2]);
                }
            // Block 2: Al x B -> same 16 accs, RAW distance 16 mma
#pragma unroll
            for (int a = 0; a < 2; a++)
#pragma unroll
                for (int fp = 0; fp < 4; fp++) {
                    mma16816(acc[a][2 * fp],     Al[a], &B[fp][0]);
                    mma16816(acc[a][2 * fp + 1], Al[a], &B[fp][2]);
                }
        }
    }

    // ---- loop 2: chunks 8..15 (B lo), AhBl (16 distinct accs per k16 already) ----
    for (int c = 8; c < 16; c++) {
        cp_wait0();
        __syncthreads();
        if (c < 15) {
            const char* src = (const char*)g_W2l + (c + 1 - 8) * 16384;
            char* dst = sm + SB + ((c + 1) & 1) * 16384;
#pragma unroll
            for (int i = 0; i < 4; i++) {
                int o = (t + i * NTHREAD) * 16;
                cp_async16(dst + o, src + o);
            }
            cp_commit();
        }
        const int kc = c - 8;
        const u32 pB  = smb + SB + (u32)(c & 1) * 16384u;
        const u32 pAh = smb + SA_H + (u32)(kc >> 1) * 8192u;
#pragma unroll
        for (int ks2 = 0; ks2 < 2; ks2++) {
            const u32 ktA = (u32)(((kc & 1) * 2 + ks2) * 2) + a_kt;
            const u32 uB  = (u32)(ks2 * 2) + b_kt;
            u32 Ah[2][4], B[4][4];
#pragma unroll
            for (int a = 0; a < 2; a++) {
                u32 ad = arow[a] + ((ktA ^ asx[a]) << 4);
                ldsm4(Ah[a][0], Ah[a][1], Ah[a][2], Ah[a][3], pAh + ad);
            }
#pragma unroll
            for (int fp = 0; fp < 4; fp++) {
                u32 bd = bline[fp] + (((uB + bhi) ^ bx[fp]) << 4);
                ldsm4(B[fp][0], B[fp][1], B[fp][2], B[fp][3], pB + bd);
            }
#pragma unroll
            for (int a = 0; a < 2; a++)
#pragma unroll
                for (int fp = 0; fp < 4; fp++) {
                    mma16816(acc[a][2 * fp],     Ah[a], &B[fp][0]);
                    mma16816(acc[a][2 * fp + 1], Ah[a], &B[fp][2]);
                }
        }
    }
    __syncthreads();                          // A hi dead -> parts may alias it

    // ---- epilogue: bias + relu + layer-3 partials + quad reduce ----
    {
        const int nw = w >> 1;                 // 0..3 (n-warp group)
        const int cbase = n0 + (lane & 3) * 2;
#pragma unroll
        for (int a = 0; a < 2; a++) {
#pragma unroll
            for (int h = 0; h < 2; h++) {
                u64 p[12];
#pragma unroll
                for (int o = 0; o < 12; o++) p[o] = 0;
#pragma unroll
                for (int f = 0; f < 8; f++) {
                    const int col = cbase + 8 * f;
                    float h0 = fmaxf(acc[a][f][2 * h]     + b2s[col],     0.0f);
                    float h1 = fmaxf(acc[a][f][2 * h + 1] + b2s[col + 1], 0.0f);
                    const u64 hh = pack2(h0, h1);
                    const u64* wv = w3p + (col >> 1) * 12;
#pragma unroll
                    for (int o = 0; o < 12; o++) p[o] = fma2(wv[o], hh, p[o]);
                }
                float v[12];
#pragma unroll
                for (int o = 0; o < 12; o++) {
                    float lo, hi;
                    unpack2(p[o], lo, hi);
                    v[o] = lo + hi;
                    v[o] += __shfl_xor_sync(0xffffffffu, v[o], 1);
                    v[o] += __shfl_xor_sync(0xffffffffu, v[o], 2);
                }
                if ((lane & 3) == 0) {
                    const int row = m0 + a * 16 + h * 8 + (lane >> 2);
                    float* dst = part + (nw * 64 + row) * 12;
#pragma unroll
                    for (int o = 0; o < 12; o++) dst[o] = v[o];
                }
            }
        }
    }
    __syncthreads();

    // ---- constraint epilogue: threads 0..63, one row each ----
    if (t < TROWS) {
        const float* xi = inp + (rowBase + t) * 12;
        float xo[12];
#pragma unroll
        for (int o = 0; o < 12; o++) {
            xo[o] = __ldg(b3 + o) + part[t * 12 + o] + part[(64 + t) * 12 + o]
                  + part[(128 + t) * 12 + o] + part[(192 + t) * 12 + o];
        }

        float p0 = tanhf(xo[0]), p1 = tanhf(xo[1]), p2 = tanhf(xo[2]);
        float v0 = tanhf(xo[3]), v1 = tanhf(xo[4]), v2 = tanhf(xo[5]);
        float pts = 1.0f / (1.0f + expf(-xo[6]));
        float c0 = tanhf(xo[7]), c1 = tanhf(xo[8]), c2 = tanhf(xo[9]);
        float s0 = tanhf(xo[10]), s1 = tanhf(xo[11]);

        float dist = sqrtf(p0 * p0 + p1 * p1 + p2 * p2);
        float pinv = (dist > 1.0f) ? (1.0f / dist) : 1.0f;
        p0 *= pinv; p1 *= pinv; p2 *= pinv;

        const float prev = xi[6];
        float ptsc = (pts > 1.0f) ? 1.0f : pts;
        ptsc = (pts < prev) ? prev : ptsc;

        const float d0 = c0 - xi[7], d1 = c1 - xi[8], d2 = c2 - xi[9];
        const float e0 = xi[0] - xi[7], e1 = xi[1] - xi[8], e2 = xi[2] - xi[9];
        const float en = sqrtf(e0 * e0 + e1 * e1 + e2 * e2);
        const float n0f = e0 / en, n1f = e1 / en, n2f = e2 / en;
        const float dd = d0 * e0 + d1 * e1 + d2 * e2;
        const float o0 = (dd > 0.0f) ? (c0 - n0f) : c0;
        const float o1 = (dd > 0.0f) ? (c1 - n1f) : c1;
        const float o2 = (dd > 0.0f) ? (c2 - n2f) : c2;
        const float cd = sqrtf(o0 * o0 + o1 * o1 + o2 * o2);
        float q0, q1, q2;
        if (cd > 1.0f) { const float ci = 1.0f / cd; q0 = o0 * ci; q1 = o1 * ci; q2 = o2 * ci; }
        else           { q0 = c0; q1 = c1; q2 = c2; }

        const float sn = sqrtf(s0 * s0 + s1 * s1);
        s0 /= sn; s1 /= sn;

        float* op = out + (rowBase + t) * 12;
        float4* ov = reinterpret_cast<float4*>(op);
        ov[0] = make_float4(p0, p1, p2, v0);
        ov[1] = make_float4(v1, v2, ptsc, q0);
        ov[2] = make_float4(q1, q2, s0, s1);
    }
}

extern "C" void kernel_launch(void* const* d_in, const int* in_sizes, int n_in,
                              void* d_out, int out_size)
{
    (void)in_sizes; (void)n_in; (void)out_size;
    const float* inp = (const float*)d_in[0];
    const float* W1  = (const float*)d_in[1];
    const float* b1  = (const float*)d_in[2];
    const float* W2  = (const float*)d_in[3];
    const float* b2  = (const float*)d_in[4];
    const float* W3  = (const float*)d_in[5];
    const float* b3  = (const float*)d_in[6];
    float* out = (float*)d_out;

    prep_w2<<<256, 256>>>(W2);

    cudaFuncSetAttribute(mlp_main, cudaFuncAttributeMaxDynamicSharedMemorySize, SMEM_BYTES);
    mlp_main<<<BATCH / TROWS, NTHREAD, SMEM_BYTES>>>(inp, W1, b1, b2, W3, b3, out);
}

// round 16
// speedup vs baseline: 1.1802x; 1.0683x over previous
#include <cuda_runtime.h>
#include <cuda_bf16.h>
#include <math.h>
#include <stdint.h>

// Fused ConstrainedMLP: 262144 x (12 -> 256 relu -> 256 relu -> 12) + constraints.
// R15: merged 3-term mainloop. 16 k16-chunks; per chunk: Ah/Al loaded ONCE, then
// AhBh + AlBh + AhBl (48 mma). B in 16 chunks of (8KB hi + 8KB lo), double-buffered.
// New B layout makes per-fragment B addresses chunk-invariant (zero per-step XOR).
// TROWS=64, 256 threads (8 warps 2Mx4N m32n64), 2 CTAs/SM.

#define BATCH    262144
#define TROWS    64
#define NTHREAD  256

typedef unsigned long long u64;
typedef unsigned int u32;

// ---------- helpers ----------
__device__ __forceinline__ u64 fma2(u64 a, u64 b, u64 c) {
    u64 d;
    asm("fma.rn.f32x2 %0, %1, %2, %3;" : "=l"(d) : "l"(a), "l"(b), "l"(c));
    return d;
}
__device__ __forceinline__ u64 pack2(float x, float y) {
    u64 r;
    asm("mov.b64 %0, {%1, %2};" : "=l"(r) : "f"(x), "f"(y));
    return r;
}
__device__ __forceinline__ void unpack2(u64 v, float& x, float& y) {
    asm("mov.b64 {%0, %1}, %2;" : "=f"(x), "=f"(y) : "l"(v));
}
__device__ __forceinline__ u32 smem_u32(const void* p) {
    u32 a;
    asm("{ .reg .u64 t; cvta.to.shared.u64 t, %1; cvt.u32.u64 %0, t; }" : "=r"(a) : "l"(p));
    return a;
}
__device__ __forceinline__ void cp_async16(char* smem_dst, const char* gsrc) {
    u32 s = smem_u32(smem_dst);
    asm volatile("cp.async.cg.shared.global [%0], [%1], 16;" :: "r"(s), "l"(gsrc));
}
__device__ __forceinline__ void cp_commit() { asm volatile("cp.async.commit_group;"); }
__device__ __forceinline__ void cp_wait0()  { asm volatile("cp.async.wait_group 0;" ::: "memory"); }

__device__ __forceinline__ void ldsm4(u32& r0, u32& r1, u32& r2, u32& r3, u32 addr) {
    asm volatile("ldmatrix.sync.aligned.m8n8.x4.shared.b16 {%0,%1,%2,%3}, [%4];"
                 : "=r"(r0), "=r"(r1), "=r"(r2), "=r"(r3) : "r"(addr));
}
__device__ __forceinline__ void mma16816(float* d, const u32* a, const u32* b) {
    asm volatile(
        "mma.sync.aligned.m16n8k16.row.col.f32.bf16.bf16.f32 "
        "{%0,%1,%2,%3}, {%4,%5,%6,%7}, {%8,%9}, {%0,%1,%2,%3};"
        : "+f"(d[0]), "+f"(d[1]), "+f"(d[2]), "+f"(d[3])
        : "r"(a[0]), "r"(a[1]), "r"(a[2]), "r"(a[3]), "r"(b[0]), "r"(b[1]));
}

// ---------- W2^T bf16 hi/lo images, 16 chunks of 8KB (one k16 each) ----------
// Per chunk: row = n>>2 (64 rows x 128B), slot s = ((n&3)*2 + u) ^ (row&7),
// u = (k&15)>>3, byte (k&7)*2. Conflict-free for ldsm over 8 consecutive n.
__device__ __align__(128) unsigned short g_W2h[65536];
__device__ __align__(128) unsigned short g_W2l[65536];

__global__ void prep_w2(const float* __restrict__ W2) {
    int i = blockIdx.x * 256 + threadIdx.x;   // i = k*256 + n over W2[k][n]
    int k = i >> 8, n = i & 255;
    float w = W2[i];
    __nv_bfloat16 hb = __float2bfloat16(w);
    __nv_bfloat16 lb = __float2bfloat16(w - __bfloat162float(hb));
    u32 hc = (u32)k >> 4, kl = (u32)k & 15, u = kl >> 3, row = (u32)n >> 2;
    u32 s = ((((u32)n & 3) << 1) + u) ^ (row & 7);
    u32 off = hc * 8192u + row * 128u + s * 16u + (kl & 7) * 2u;
    g_W2h[off >> 1] = __bfloat16_as_ushort(hb);
    g_W2l[off >> 1] = __bfloat16_as_ushort(lb);
}

// ---------- smem byte offsets (total 112640 B -> 2 CTAs/SM) ----------
#define SA_H    0         // A hi: 4 chunks x 8192 = 32768
#define SA_L    32768     // A lo: 32768
#define SB      65536     // B double buffer: 2 x (8KB hi + 8KB lo) = 32768
#define SW3P    98304     // W3 pairs 128*12 u64 = 12288
#define SB1     110592    // 1024
#define SB2     111616    // 1024
#define SMEM_BYTES 112640
#define SW1P    (SB + 16384)   // W1 pairs (12288 B) alias B buf1 (dead after layer 1)
#define SPART   SA_H           // layer-3 partials (12288 B) alias A hi (after all mma)

__global__ __launch_bounds__(NTHREAD, 2)
void mlp_main(const float* __restrict__ inp,
              const float* __restrict__ W1,
              const float* __restrict__ b1,
              const float* __restrict__ b2,
              const float* __restrict__ W3,
              const float* __restrict__ b3,
              float* __restrict__ out)
{
    extern __shared__ char sm[];
    u64*   w3p  = (u64*)  (sm + SW3P);
    u64*   w1p  = (u64*)  (sm + SW1P);
    float* part = (float*)(sm + SPART);
    float* b1s  = (float*)(sm + SB1);
    float* b2s  = (float*)(sm + SB2);
    const u32 smb = smem_u32(sm);
    const int t = threadIdx.x;
    const long rowBase = (long)blockIdx.x * TROWS;

    // ---- prefetch B chunk 0 (8KB hi + 8KB lo) into buf0 ----
    {
#pragma unroll
        for (int i = 0; i < 2; i++) {
            int o = (t + i * NTHREAD) * 16;
            cp_async16(sm + SB + o, (const char*)g_W2h + o);
            cp_async16(sm + SB + 8192 + o, (const char*)g_W2l + o);
        }
        cp_commit();
    }

    // ---- staging ----
    for (int i = t; i < 1536; i += NTHREAD) {        // W1 pairs (alias B buf1)
        int jp = i / 12, k = i % 12;
        w1p[i] = pack2(W1[k * 256 + 2 * jp], W1[k * 256 + 2 * jp + 1]);
    }
    for (int i = t; i < 1536; i += NTHREAD) {        // W3 pairs
        int k2 = i / 12, o = i % 12;
        w3p[i] = pack2(W3[(2 * k2) * 12 + o], W3[(2 * k2 + 1) * 12 + o]);
    }
    for (int i = t; i < 256; i += NTHREAD) { b1s[i] = b1[i]; b2s[i] = b2[i]; }
    __syncthreads();

    // ---- layer 1: thread t -> row r = t&63, units [ug*64, ug*64+64) ----
    {
        const int r = t & 63, ug = t >> 6;
        const float* xrow = inp + (rowBase + r) * 12;
        u64 xx[12];
#pragma unroll
        for (int k = 0; k < 12; k++) { float x = xrow[k]; xx[k] = pack2(x, x); }
        char* ahc = sm + SA_H + ug * 8192;
        char* alc = sm + SA_L + ug * 8192;
#pragma unroll 4
        for (int i = 0; i < 32; i++) {
            const int kl0 = 2 * i;
            const int j = ug * 64 + kl0;
            const u64* wp = w1p + (j >> 1) * 12;
            u64 acc2 = pack2(b1s[j], b1s[j + 1]);
#pragma unroll
            for (int k = 0; k < 12; k++) acc2 = fma2(wp[k], xx[k], acc2);
            float a0, a1;
            unpack2(acc2, a0, a1);
            a0 = fmaxf(a0, 0.0f); a1 = fmaxf(a1, 0.0f);
            __nv_bfloat16 h0 = __float2bfloat16(a0), h1 = __float2bfloat16(a1);
            __nv_bfloat16 l0 = __float2bfloat16(a0 - __bfloat162float(h0));
            __nv_bfloat16 l1 = __float2bfloat16(a1 - __bfloat162float(h1));
            u32 hw = (u32)__bfloat16_as_ushort(h0) | ((u32)__bfloat16_as_ushort(h1) << 16);
            u32 lw = (u32)__bfloat16_as_ushort(l0) | ((u32)__bfloat16_as_ushort(l1) << 16);
            u32 off = ((u32)r << 7) + ((((u32)(kl0 >> 3)) ^ ((u32)r & 7)) << 4) + (((u32)kl0 & 7) << 1);
            *(u32*)(ahc + off) = hw;
            *(u32*)(alc + off) = lw;
        }
    }
    // loop-top sync of c=0 covers: A visible to all, w1p dead before buf1 prefetch.

    // ---- warp mma geometry: 8 warps = 2M x 4N, warp tile m32 x n64 ----
    const int w = t >> 5, lane = t & 31;
    const int m0 = (w & 1) * 32, n0 = (w >> 1) * 64;
    const int lt = lane >> 3, l8 = lane & 7;

    u32 arow[2], asx[2];
#pragma unroll
    for (int a = 0; a < 2; a++) {
        u32 row = (u32)(m0 + a * 16 + ((lt & 1) << 3) + l8);
        arow[a] = row << 7;
        asx[a]  = row & 7;
    }
    const u32 a_kt = (u32)(lt >> 1);
    const u32 b_kt = (u32)(lt & 1);
    // B fragment addresses: chunk-invariant (new layout)
    u32 baddr[4];
#pragma unroll
    for (int fp = 0; fp < 4; fp++) {
        u32 n = (u32)(n0 + fp * 16 + ((lt >> 1) << 3) + l8);
        u32 row = n >> 2;
        baddr[fp] = row * 128u + (((((n & 3) << 1) + b_kt) ^ (row & 7)) << 4);
    }

    float acc[2][8][4];
#pragma unroll
    for (int a = 0; a < 2; a++)
#pragma unroll
        for (int f = 0; f < 8; f++)
#pragma unroll
            for (int q = 0; q < 4; q++) acc[a][f][q] = 0.0f;

    // ---- merged mainloop: 16 k16-chunks; per chunk AhBh + AlBh + AhBl ----
    for (int c = 0; c < 16; c++) {
        cp_wait0();
        __syncthreads();                       // chunk c visible; other buf free
        if (c < 15) {
            const char* srcH = (const char*)g_W2h + (c + 1) * 8192;
            const char* srcL = (const char*)g_W2l + (c + 1) * 8192;
            char* dst = sm + SB + ((c + 1) & 1) * 16384;
#pragma unroll
            for (int i = 0; i < 2; i++) {
                int o = (t + i * NTHREAD) * 16;
                cp_async16(dst + o, srcH + o);
                cp_async16(dst + 8192 + o, srcL + o);
            }
            cp_commit();
        }
        const u32 pB  = smb + SB + (u32)(c & 1) * 16384u;
        const u32 pAh = smb + SA_H + (u32)(c >> 2) * 8192u;
        const u32 pAl = smb + SA_L + (u32)(c >> 2) * 8192u;
        const u32 ktA = (u32)((c & 3) * 2) + a_kt;

        u32 Ah[2][4], Al[2][4], B[4][4];
#pragma unroll
        for (int a = 0; a < 2; a++) {
            u32 ad = arow[a] + ((ktA ^ asx[a]) << 4);
            ldsm4(Ah[a][0], Ah[a][1], Ah[a][2], Ah[a][3], pAh + ad);
            ldsm4(Al[a][0], Al[a][1], Al[a][2], Al[a][3], pAl + ad);
        }
        // B hi
#pragma unroll
        for (int fp = 0; fp < 4; fp++)
            ldsm4(B[fp][0], B[fp][1], B[fp][2], B[fp][3], pB + baddr[fp]);
#pragma unroll
        for (int a = 0; a < 2; a++)
#pragma unroll
            for (int fp = 0; fp < 4; fp++) {
                mma16816(acc[a][2 * fp],     Ah[a], &B[fp][0]);
                mma16816(acc[a][2 * fp + 1], Ah[a], &B[fp][2]);
            }
#pragma unroll
        for (int a = 0; a < 2; a++)
#pragma unroll
            for (int fp = 0; fp < 4; fp++) {
                mma16816(acc[a][2 * fp],     Al[a], &B[fp][0]);
                mma16816(acc[a][2 * fp + 1], Al[a], &B[fp][2]);
            }
        // B lo (reuse B regs)
#pragma unroll
        for (int fp = 0; fp < 4; fp++)
            ldsm4(B[fp][0], B[fp][1], B[fp][2], B[fp][3], pB + 8192u + baddr[fp]);
#pragma unroll
        for (int a = 0; a < 2; a++)
#pragma unroll
            for (int fp = 0; fp < 4; fp++) {
                mma16816(acc[a][2 * fp],     Ah[a], &B[fp][0]);
                mma16816(acc[a][2 * fp + 1], Ah[a], &B[fp][2]);
            }
    }
    __syncthreads();                          // A hi dead -> parts may alias it

    // ---- epilogue: bias + relu + layer-3 partials + quad reduce ----
    {
        const int nw = w >> 1;                 // 0..3 (n-warp group)
        const int cbase = n0 + (lane & 3) * 2;
#pragma unroll
        for (int a = 0; a < 2; a++) {
#pragma unroll
            for (int h = 0; h < 2; h++) {
                u64 p[12];
#pragma unroll
                for (int o = 0; o < 12; o++) p[o] = 0;
#pragma unroll
                for (int f = 0; f < 8; f++) {
                    const int col = cbase + 8 * f;
                    float h0 = fmaxf(acc[a][f][2 * h]     + b2s[col],     0.0f);
                    float h1 = fmaxf(acc[a][f][2 * h + 1] + b2s[col + 1], 0.0f);
                    const u64 hh = pack2(h0, h1);
                    const u64* wv = w3p + (col >> 1) * 12;
#pragma unroll
                    for (int o = 0; o < 12; o++) p[o] = fma2(wv[o], hh, p[o]);
                }
                float v[12];
#pragma unroll
                for (int o = 0; o < 12; o++) {
                    float lo, hi;
                    unpack2(p[o], lo, hi);
                    v[o] = lo + hi;
                    v[o] += __shfl_xor_sync(0xffffffffu, v[o], 1);
                    v[o] += __shfl_xor_sync(0xffffffffu, v[o], 2);
                }
                if ((lane & 3) == 0) {
                    const int row = m0 + a * 16 + h * 8 + (lane >> 2);
                    float* dst = part + (nw * 64 + row) * 12;
#pragma unroll
                    for (int o = 0; o < 12; o++) dst[o] = v[o];
                }
            }
        }
    }
    __syncthreads();

    // ---- constraint epilogue: threads 0..63, one row each ----
    if (t < TROWS) {
        const float* xi = inp + (rowBase + t) * 12;
        float xo[12];
#pragma unroll
        for (int o = 0; o < 12; o++) {
            xo[o] = __ldg(b3 + o) + part[t * 12 + o] + part[(64 + t) * 12 + o]
                  + part[(128 + t) * 12 + o] + part[(192 + t) * 12 + o];
        }

        float p0 = tanhf(xo[0]), p1 = tanhf(xo[1]), p2 = tanhf(xo[2]);
        float v0 = tanhf(xo[3]), v1 = tanhf(xo[4]), v2 = tanhf(xo[5]);
        float pts = 1.0f / (1.0f + expf(-xo[6]));
        float c0 = tanhf(xo[7]), c1 = tanhf(xo[8]), c2 = tanhf(xo[9]);
        float s0 = tanhf(xo[10]), s1 = tanhf(xo[11]);

        float dist = sqrtf(p0 * p0 + p1 * p1 + p2 * p2);
        float pinv = (dist > 1.0f) ? (1.0f / dist) : 1.0f;
        p0 *= pinv; p1 *= pinv; p2 *= pinv;

        const float prev = xi[6];
        float ptsc = (pts > 1.0f) ? 1.0f : pts;
        ptsc = (pts < prev) ? prev : ptsc;

        const float d0 = c0 - xi[7], d1 = c1 - xi[8], d2 = c2 - xi[9];
        const float e0 = xi[0] - xi[7], e1 = xi[1] - xi[8], e2 = xi[2] - xi[9];
        const float en = sqrtf(e0 * e0 + e1 * e1 + e2 * e2);
        const float n0f = e0 / en, n1f = e1 / en, n2f = e2 / en;
        const float dd = d0 * e0 + d1 * e1 + d2 * e2;
        const float o0 = (dd > 0.0f) ? (c0 - n0f) : c0;
        const float o1 = (dd > 0.0f) ? (c1 - n1f) : c1;
        const float o2 = (dd > 0.0f) ? (c2 - n2f) : c2;
        const float cd = sqrtf(o0 * o0 + o1 * o1 + o2 * o2);
        float q0, q1, q2;
        if (cd > 1.0f) { const float ci = 1.0f / cd; q0 = o0 * ci; q1 = o1 * ci; q2 = o2 * ci; }
        else           { q0 = c0; q1 = c1; q2 = c2; }

        const float sn = sqrtf(s0 * s0 + s1 * s1);
        s0 /= sn; s1 /= sn;

        float* op = out + (rowBase + t) * 12;
        float4* ov = reinterpret_cast<float4*>(op);
        ov[0] = make_float4(p0, p1, p2, v0);
        ov[1] = make_float4(v1, v2, ptsc, q0);
        ov[2] = make_float4(q1, q2, s0, s1);
    }
}

extern "C" void kernel_launch(void* const* d_in, const int* in_sizes, int n_in,
                              void* d_out, int out_size)
{
    (void)in_sizes; (void)n_in; (void)out_size;
    const float* inp = (const float*)d_in[0];
    const float* W1  = (const float*)d_in[1];
    const float* b1  = (const float*)d_in[2];
    const float* W2  = (const float*)d_in[3];
    const float* b2  = (const float*)d_in[4];
    const float* W3  = (const float*)d_in[5];
    const float* b3  = (const float*)d_in[6];
    float* out = (float*)d_out;

    prep_w2<<<256, 256>>>(W2);

    cudaFuncSetAttribute(mlp_main, cudaFuncAttributeMaxDynamicSharedMemorySize, SMEM_BYTES);
    mlp_main<<<BATCH / TROWS, NTHREAD, SMEM_BYTES>>>(inp, W1, b1, b2, W3, b3, out);
}

// round 17
// speedup vs baseline: 1.2836x; 1.0876x over previous
#include <cuda_runtime.h>
#include <cuda_bf16.h>
#include <math.h>
#include <stdint.h>

// Fused ConstrainedMLP: 262144 x (12 -> 256 relu -> 256 relu -> 12) + constraints.
// R16: R15 merged 3-term mainloop unchanged. Scalar-phase LDS halved:
//  - layer 1: 2 rows/thread -> W1 pair loads amortized over 2 rows (384->192 LDS)
//  - epilogue: per-a passes, w3p loaded once per a for both h halves (384->192 LDS)
// TROWS=64, 256 threads (8 warps 2Mx4N m32n64), 2 CTAs/SM.

#define BATCH    262144
#define TROWS    64
#define NTHREAD  256

typedef unsigned long long u64;
typedef unsigned int u32;

// ---------- helpers ----------
__device__ __forceinline__ u64 fma2(u64 a, u64 b, u64 c) {
    u64 d;
    asm("fma.rn.f32x2 %0, %1, %2, %3;" : "=l"(d) : "l"(a), "l"(b), "l"(c));
    return d;
}
__device__ __forceinline__ u64 pack2(float x, float y) {
    u64 r;
    asm("mov.b64 %0, {%1, %2};" : "=l"(r) : "f"(x), "f"(y));
    return r;
}
__device__ __forceinline__ void unpack2(u64 v, float& x, float& y) {
    asm("mov.b64 {%0, %1}, %2;" : "=f"(x), "=f"(y) : "l"(v));
}
__device__ __forceinline__ u32 smem_u32(const void* p) {
    u32 a;
    asm("{ .reg .u64 t; cvta.to.shared.u64 t, %1; cvt.u32.u64 %0, t; }" : "=r"(a) : "l"(p));
    return a;
}
__device__ __forceinline__ void cp_async16(char* smem_dst, const char* gsrc) {
    u32 s = smem_u32(smem_dst);
    asm volatile("cp.async.cg.shared.global [%0], [%1], 16;" :: "r"(s), "l"(gsrc));
}
__device__ __forceinline__ void cp_commit() { asm volatile("cp.async.commit_group;"); }
__device__ __forceinline__ void cp_wait0()  { asm volatile("cp.async.wait_group 0;" ::: "memory"); }

__device__ __forceinline__ void ldsm4(u32& r0, u32& r1, u32& r2, u32& r3, u32 addr) {
    asm volatile("ldmatrix.sync.aligned.m8n8.x4.shared.b16 {%0,%1,%2,%3}, [%4];"
                 : "=r"(r0), "=r"(r1), "=r"(r2), "=r"(r3) : "r"(addr));
}
__device__ __forceinline__ void mma16816(float* d, const u32* a, const u32* b) {
    asm volatile(
        "mma.sync.aligned.m16n8k16.row.col.f32.bf16.bf16.f32 "
        "{%0,%1,%2,%3}, {%4,%5,%6,%7}, {%8,%9}, {%0,%1,%2,%3};"
        : "+f"(d[0]), "+f"(d[1]), "+f"(d[2]), "+f"(d[3])
        : "r"(a[0]), "r"(a[1]), "r"(a[2]), "r"(a[3]), "r"(b[0]), "r"(b[1]));
}

// ---------- W2^T bf16 hi/lo images, 16 chunks of 8KB (one k16 each) ----------
// Per chunk: row = n>>2 (64 rows x 128B), slot s = ((n&3)*2 + u) ^ (row&7),
// u = (k&15)>>3, byte (k&7)*2. Conflict-free for ldsm over 8 consecutive n.
__device__ __align__(128) unsigned short g_W2h[65536];
__device__ __align__(128) unsigned short g_W2l[65536];

__global__ void prep_w2(const float* __restrict__ W2) {
    int i = blockIdx.x * 256 + threadIdx.x;   // i = k*256 + n over W2[k][n]
    int k = i >> 8, n = i & 255;
    float w = W2[i];
    __nv_bfloat16 hb = __float2bfloat16(w);
    __nv_bfloat16 lb = __float2bfloat16(w - __bfloat162float(hb));
    u32 hc = (u32)k >> 4, kl = (u32)k & 15, u = kl >> 3, row = (u32)n >> 2;
    u32 s = ((((u32)n & 3) << 1) + u) ^ (row & 7);
    u32 off = hc * 8192u + row * 128u + s * 16u + (kl & 7) * 2u;
    g_W2h[off >> 1] = __bfloat16_as_ushort(hb);
    g_W2l[off >> 1] = __bfloat16_as_ushort(lb);
}

// ---------- smem byte offsets (total 112640 B -> 2 CTAs/SM) ----------
#define SA_H    0         // A hi: 4 chunks x 8192 = 32768
#define SA_L    32768     // A lo: 32768
#define SB      65536     // B double buffer: 2 x (8KB hi + 8KB lo) = 32768
#define SW3P    98304     // W3 pairs 128*12 u64 = 12288
#define SB1     110592    // 1024
#define SB2     111616    // 1024
#define SMEM_BYTES 112640
#define SW1P    (SB + 16384)   // W1 pairs (12288 B) alias B buf1 (dead after layer 1)
#define SPART   SA_H           // layer-3 partials (12288 B) alias A hi (after all mma)

__global__ __launch_bounds__(NTHREAD, 2)
void mlp_main(const float* __restrict__ inp,
              const float* __restrict__ W1,
              const float* __restrict__ b1,
              const float* __restrict__ b2,
              const float* __restrict__ W3,
              const float* __restrict__ b3,
              float* __restrict__ out)
{
    extern __shared__ char sm[];
    u64*   w3p  = (u64*)  (sm + SW3P);
    u64*   w1p  = (u64*)  (sm + SW1P);
    float* part = (float*)(sm + SPART);
    float* b1s  = (float*)(sm + SB1);
    float* b2s  = (float*)(sm + SB2);
    const u32 smb = smem_u32(sm);
    const int t = threadIdx.x;
    const long rowBase = (long)blockIdx.x * TROWS;

    // ---- prefetch B chunk 0 (8KB hi + 8KB lo) into buf0 ----
    {
#pragma unroll
        for (int i = 0; i < 2; i++) {
            int o = (t + i * NTHREAD) * 16;
            cp_async16(sm + SB + o, (const char*)g_W2h + o);
            cp_async16(sm + SB + 8192 + o, (const char*)g_W2l + o);
        }
        cp_commit();
    }

    // ---- staging ----
    for (int i = t; i < 1536; i += NTHREAD) {        // W1 pairs (alias B buf1)
        int jp = i / 12, k = i % 12;
        w1p[i] = pack2(W1[k * 256 + 2 * jp], W1[k * 256 + 2 * jp + 1]);
    }
    for (int i = t; i < 1536; i += NTHREAD) {        // W3 pairs
        int k2 = i / 12, o = i % 12;
        w3p[i] = pack2(W3[(2 * k2) * 12 + o], W3[(2 * k2 + 1) * 12 + o]);
    }
    for (int i = t; i < 256; i += NTHREAD) { b1s[i] = b1[i]; b2s[i] = b2[i]; }
    __syncthreads();

    // ---- layer 1: thread t -> rows (t&31, t&31+32), units [ug*32, ug*32+32) ----
    {
        const int r0 = t & 31, ug = t >> 5;          // ug 0..7
        const float* xrow0 = inp + (rowBase + r0) * 12;
        const float* xrow1 = inp + (rowBase + r0 + 32) * 12;
        u64 xx0[12], xx1[12];
#pragma unroll
        for (int k = 0; k < 12; k++) {
            float x0 = xrow0[k], x1 = xrow1[k];
            xx0[k] = pack2(x0, x0);
            xx1[k] = pack2(x1, x1);
        }
#pragma unroll 4
        for (int i = 0; i < 16; i++) {
            const int kl0 = 2 * i;
            const int j = ug * 32 + kl0;             // global unit pair start
            const int chunk = j >> 6, klc = j & 63;  // chunk + k-offset within chunk
            char* ahc = sm + SA_H + chunk * 8192;
            char* alc = sm + SA_L + chunk * 8192;
            const u64* wp = w1p + (j >> 1) * 12;
            const u64 bb = pack2(b1s[j], b1s[j + 1]);
            u64 acc0 = bb, acc1 = bb;
#pragma unroll
            for (int k = 0; k < 12; k++) {
                const u64 wk = wp[k];
                acc0 = fma2(wk, xx0[k], acc0);
                acc1 = fma2(wk, xx1[k], acc1);
            }
#pragma unroll
            for (int rr = 0; rr < 2; rr++) {
                float a0, a1;
                unpack2(rr ? acc1 : acc0, a0, a1);
                a0 = fmaxf(a0, 0.0f); a1 = fmaxf(a1, 0.0f);
                __nv_bfloat16 h0 = __float2bfloat16(a0), h1 = __float2bfloat16(a1);
                __nv_bfloat16 l0 = __float2bfloat16(a0 - __bfloat162float(h0));
                __nv_bfloat16 l1 = __float2bfloat16(a1 - __bfloat162float(h1));
                u32 hw = (u32)__bfloat16_as_ushort(h0) | ((u32)__bfloat16_as_ushort(h1) << 16);
                u32 lw = (u32)__bfloat16_as_ushort(l0) | ((u32)__bfloat16_as_ushort(l1) << 16);
                const u32 r = (u32)(r0 + rr * 32);
                u32 off = (r << 7) + ((((u32)(klc >> 3)) ^ (r & 7)) << 4) + (((u32)klc & 7) << 1);
                *(u32*)(ahc + off) = hw;
                *(u32*)(alc + off) = lw;
            }
        }
    }
    // loop-top sync of c=0 covers: A visible to all, w1p dead before buf1 prefetch.

    // ---- warp mma geometry: 8 warps = 2M x 4N, warp tile m32 x n64 ----
    const int w = t >> 5, lane = t & 31;
    const int m0 = (w & 1) * 32, n0 = (w >> 1) * 64;
    const int lt = lane >> 3, l8 = lane & 7;

    u32 arow[2], asx[2];
#pragma unroll
    for (int a = 0; a < 2; a++) {
        u32 row = (u32)(m0 + a * 16 + ((lt & 1) << 3) + l8);
        arow[a] = row << 7;
        asx[a]  = row & 7;
    }
    const u32 a_kt = (u32)(lt >> 1);
    const u32 b_kt = (u32)(lt & 1);
    // B fragment addresses: chunk-invariant
    u32 baddr[4];
#pragma unroll
    for (int fp = 0; fp < 4; fp++) {
        u32 n = (u32)(n0 + fp * 16 + ((lt >> 1) << 3) + l8);
        u32 row = n >> 2;
        baddr[fp] = row * 128u + (((((n & 3) << 1) + b_kt) ^ (row & 7)) << 4);
    }

    float acc[2][8][4];
#pragma unroll
    for (int a = 0; a < 2; a++)
#pragma unroll
        for (int f = 0; f < 8; f++)
#pragma unroll
            for (int q = 0; q < 4; q++) acc[a][f][q] = 0.0f;

    // ---- merged mainloop: 16 k16-chunks; per chunk AhBh + AlBh + AhBl ----
    for (int c = 0; c < 16; c++) {
        cp_wait0();
        __syncthreads();                       // chunk c visible; other buf free
        if (c < 15) {
            const char* srcH = (const char*)g_W2h + (c + 1) * 8192;
            const char* srcL = (const char*)g_W2l + (c + 1) * 8192;
            char* dst = sm + SB + ((c + 1) & 1) * 16384;
#pragma unroll
            for (int i = 0; i < 2; i++) {
                int o = (t + i * NTHREAD) * 16;
                cp_async16(dst + o, srcH + o);
                cp_async16(dst + 8192 + o, srcL + o);
            }
            cp_commit();
        }
        const u32 pB  = smb + SB + (u32)(c & 1) * 16384u;
        const u32 pAh = smb + SA_H + (u32)(c >> 2) * 8192u;
        const u32 pAl = smb + SA_L + (u32)(c >> 2) * 8192u;
        const u32 ktA = (u32)((c & 3) * 2) + a_kt;

        u32 Ah[2][4], Al[2][4], B[4][4];
#pragma unroll
        for (int a = 0; a < 2; a++) {
            u32 ad = arow[a] + ((ktA ^ asx[a]) << 4);
            ldsm4(Ah[a][0], Ah[a][1], Ah[a][2], Ah[a][3], pAh + ad);
            ldsm4(Al[a][0], Al[a][1], Al[a][2], Al[a][3], pAl + ad);
        }
        // B hi
#pragma unroll
        for (int fp = 0; fp < 4; fp++)
            ldsm4(B[fp][0], B[fp][1], B[fp][2], B[fp][3], pB + baddr[fp]);
#pragma unroll
        for (int a = 0; a < 2; a++)
#pragma unroll
            for (int fp = 0; fp < 4; fp++) {
                mma16816(acc[a][2 * fp],     Ah[a], &B[fp][0]);
                mma16816(acc[a][2 * fp + 1], Ah[a], &B[fp][2]);
            }
#pragma unroll
        for (int a = 0; a < 2; a++)
#pragma unroll
            for (int fp = 0; fp < 4; fp++) {
                mma16816(acc[a][2 * fp],     Al[a], &B[fp][0]);
                mma16816(acc[a][2 * fp + 1], Al[a], &B[fp][2]);
            }
        // B lo (reuse B regs)
#pragma unroll
        for (int fp = 0; fp < 4; fp++)
            ldsm4(B[fp][0], B[fp][1], B[fp][2], B[fp][3], pB + 8192u + baddr[fp]);
#pragma unroll
        for (int a = 0; a < 2; a++)
#pragma unroll
            for (int fp = 0; fp < 4; fp++) {
                mma16816(acc[a][2 * fp],     Ah[a], &B[fp][0]);
                mma16816(acc[a][2 * fp + 1], Ah[a], &B[fp][2]);
            }
    }
    __syncthreads();                          // A hi dead -> parts may alias it

    // ---- epilogue: per-a passes; w3p loaded once per a for both h halves ----
    {
        const int nw = w >> 1;                 // 0..3 (n-warp group)
        const int cbase = n0 + (lane & 3) * 2;
#pragma unroll
        for (int a = 0; a < 2; a++) {
            u64 p[2][12];
#pragma unroll
            for (int h = 0; h < 2; h++)
#pragma unroll
                for (int o = 0; o < 12; o++) p[h][o] = 0;
#pragma unroll
            for (int f = 0; f < 8; f++) {
                const int col = cbase + 8 * f;
                const float bcol0 = b2s[col], bcol1 = b2s[col + 1];
                float h00 = fmaxf(acc[a][f][0] + bcol0, 0.0f);
                float h01 = fmaxf(acc[a][f][1] + bcol1, 0.0f);
                float h10 = fmaxf(acc[a][f][2] + bcol0, 0.0f);
                float h11 = fmaxf(acc[a][f][3] + bcol1, 0.0f);
                const u64 hh0 = pack2(h00, h01);
                const u64 hh1 = pack2(h10, h11);
                const u64* wv = w3p + (col >> 1) * 12;
#pragma unroll
                for (int o = 0; o < 12; o++) {
                    const u64 wo = wv[o];
                    p[0][o] = fma2(wo, hh0, p[0][o]);
                    p[1][o] = fma2(wo, hh1, p[1][o]);
                }
            }
#pragma unroll
            for (int h = 0; h < 2; h++) {
                float v[12];
#pragma unroll
                for (int o = 0; o < 12; o++) {
                    float lo, hi;
                    unpack2(p[h][o], lo, hi);
                    v[o] = lo + hi;
                    v[o] += __shfl_xor_sync(0xffffffffu, v[o], 1);
                    v[o] += __shfl_xor_sync(0xffffffffu, v[o], 2);
                }
                if ((lane & 3) == 0) {
                    const int row = m0 + a * 16 + h * 8 + (lane >> 2);
                    float* dst = part + (nw * 64 + row) * 12;
#pragma unroll
                    for (int o = 0; o < 12; o++) dst[o] = v[o];
                }
            }
        }
    }
    __syncthreads();

    // ---- constraint epilogue: threads 0..63, one row each ----
    if (t < TROWS) {
        const float* xi = inp + (rowBase + t) * 12;
        float xo[12];
#pragma unroll
        for (int o = 0; o < 12; o++) {
            xo[o] = __ldg(b3 + o) + part[t * 12 + o] + part[(64 + t) * 12 + o]
                  + part[(128 + t) * 12 + o] + part[(192 + t) * 12 + o];
        }

        float p0 = tanhf(xo[0]), p1 = tanhf(xo[1]), p2 = tanhf(xo[2]);
        float v0 = tanhf(xo[3]), v1 = tanhf(xo[4]), v2 = tanhf(xo[5]);
        float pts = 1.0f / (1.0f + expf(-xo[6]));
        float c0 = tanhf(xo[7]), c1 = tanhf(xo[8]), c2 = tanhf(xo[9]);
        float s0 = tanhf(xo[10]), s1 = tanhf(xo[11]);

        float dist = sqrtf(p0 * p0 + p1 * p1 + p2 * p2);
        float pinv = (dist > 1.0f) ? (1.0f / dist) : 1.0f;
        p0 *= pinv; p1 *= pinv; p2 *= pinv;

        const float prev = xi[6];
        float ptsc = (pts > 1.0f) ? 1.0f : pts;
        ptsc = (pts < prev) ? prev : ptsc;

        const float d0 = c0 - xi[7], d1 = c1 - xi[8], d2 = c2 - xi[9];
        const float e0 = xi[0] - xi[7], e1 = xi[1] - xi[8], e2 = xi[2] - xi[9];
        const float en = sqrtf(e0 * e0 + e1 * e1 + e2 * e2);
        const float n0f = e0 / en, n1f = e1 / en, n2f = e2 / en;
        const float dd = d0 * e0 + d1 * e1 + d2 * e2;
        const float o0 = (dd > 0.0f) ? (c0 - n0f) : c0;
        const float o1 = (dd > 0.0f) ? (c1 - n1f) : c1;
        const float o2 = (dd > 0.0f) ? (c2 - n2f) : c2;
        const float cd = sqrtf(o0 * o0 + o1 * o1 + o2 * o2);
        float q0, q1, q2;
        if (cd > 1.0f) { const float ci = 1.0f / cd; q0 = o0 * ci; q1 = o1 * ci; q2 = o2 * ci; }
        else           { q0 = c0; q1 = c1; q2 = c2; }

        const float sn = sqrtf(s0 * s0 + s1 * s1);
        s0 /= sn; s1 /= sn;

        float* op = out + (rowBase + t) * 12;
        float4* ov = reinterpret_cast<float4*>(op);
        ov[0] = make_float4(p0, p1, p2, v0);
        ov[1] = make_float4(v1, v2, ptsc, q0);
        ov[2] = make_float4(q1, q2, s0, s1);
    }
}

extern "C" void kernel_launch(void* const* d_in, const int* in_sizes, int n_in,
                              void* d_out, int out_size)
{
    (void)in_sizes; (void)n_in; (void)out_size;
    const float* inp = (const float*)d_in[0];
    const float* W1  = (const float*)d_in[1];
    const float* b1  = (const float*)d_in[2];
    const float* W2  = (const float*)d_in[3];
    const float* b2  = (const float*)d_in[4];
    const float* W3  = (const float*)d_in[5];
    const float* b3  = (const float*)d_in[6];
    float* out = (float*)d_out;

    prep_w2<<<256, 256>>>(W2);

    cudaFuncSetAttribute(mlp_main, cudaFuncAttributeMaxDynamicSharedMemorySize, SMEM_BYTES);
    mlp_main<<<BATCH / TROWS, NTHREAD, SMEM_BYTES>>>(inp, W1, b1, b2, W3, b3, out);
}